// round 2
// baseline (speedup 1.0000x reference)
#include <cuda_runtime.h>
#include <math.h>

#define NN 100000
#define EE 1000000
#define HID 128

// ---------------- device scratch ------------------------------------------------
__device__ float g_hs_l[NN * HID];
__device__ float g_hs_g[NN * HID];
__device__ float g_as_l[NN * 4];
__device__ float g_as_g[NN * 4];
__device__ float g_ad_l[NN * 4];
__device__ float g_ad_g[NN * 4];
__device__ float g_agg[6 * NN * HID];     // [rel*2+scale][NN][128]
__device__ float g_vd[12 * HID * 4];      // [combo][k][h]
__device__ int   g_cnt[NN];
__device__ int   g_rowptr[NN + 1];
__device__ int   g_cursor[NN];
__device__ int   g_srcs[EE + NN];

#define SMEM_GEMM ((64 * 132 + 128 * 128) * 4)
#define SMEM_FUSE ((32 * 260 + 256 * 128) * 4)

__device__ __forceinline__ float lrelu(float x, float s) { return x > 0.f ? x : s * x; }
__device__ __forceinline__ float sel4(int h, float a, float b, float c, float d) {
    return h == 0 ? a : (h == 1 ? b : (h == 2 ? c : d));
}

// ---------------- Vd = W_dst[:, h*32+c] · att_dst[h, c]  → [128,4] per combo ----
__global__ void k_compute_vd(const float* __restrict__ Wl, const float* __restrict__ attl,
                             const float* __restrict__ Wg, const float* __restrict__ attg) {
    int combo = blockIdx.x;          // r*2+s
    int k = threadIdx.x;             // 0..127
    int r = combo >> 1, s = combo & 1;
    const float* W = (s ? Wg : Wl) + r * HID * HID;
    const float* att = (s ? attg : attl) + r * HID;
#pragma unroll
    for (int h = 0; h < 4; h++) {
        float sum = 0.f;
#pragma unroll
        for (int c = 0; c < 32; c++)
            sum += W[k * HID + h * 32 + c] * att[h * 32 + c];
        g_vd[combo * HID * 4 + k * 4 + h] = sum;
    }
}

// ---------------- C[M,128] = A[M,128] @ B[128,128], fp32 tiled -----------------
__global__ __launch_bounds__(256) void k_gemm(const float* __restrict__ A,
                                              const float* __restrict__ B,
                                              float* __restrict__ C, int M) {
    extern __shared__ float sm[];
    float* As = sm;                 // 64 x 132 (padded)
    float* Bs = sm + 64 * 132;      // 128 x 128
    int tid = threadIdx.x;
    int tx = tid & 15, ty = tid >> 4;
    int row0 = blockIdx.x * 64;

#pragma unroll
    for (int i = 0; i < 8; i++) {
        int fi = tid + i * 256;
        int r = fi >> 5, q = fi & 31;
        float4 v = make_float4(0.f, 0.f, 0.f, 0.f);
        if (row0 + r < M) v = *(const float4*)(A + (size_t)(row0 + r) * HID + q * 4);
        *(float4*)(As + r * 132 + q * 4) = v;
    }
#pragma unroll
    for (int i = 0; i < 16; i++) {
        int fi = tid + i * 256;
        int r = fi >> 5, q = fi & 31;
        *(float4*)(Bs + r * 128 + q * 4) = *(const float4*)(B + r * 128 + q * 4);
    }
    __syncthreads();

    float acc[4][8];
#pragma unroll
    for (int i = 0; i < 4; i++)
#pragma unroll
        for (int j = 0; j < 8; j++) acc[i][j] = 0.f;

    int ra = ty * 4, c0 = tx * 8;
#pragma unroll 8
    for (int k = 0; k < 128; k++) {
        float a[4];
#pragma unroll
        for (int i = 0; i < 4; i++) a[i] = As[(ra + i) * 132 + k];
        float4 b0 = *(float4*)(Bs + k * 128 + c0);
        float4 b1 = *(float4*)(Bs + k * 128 + c0 + 4);
        float bb[8] = {b0.x, b0.y, b0.z, b0.w, b1.x, b1.y, b1.z, b1.w};
#pragma unroll
        for (int i = 0; i < 4; i++)
#pragma unroll
            for (int j = 0; j < 8; j++) acc[i][j] += a[i] * bb[j];
    }
#pragma unroll
    for (int i = 0; i < 4; i++) {
        int row = row0 + ra + i;
        if (row < M) {
            float4 o0 = make_float4(acc[i][0], acc[i][1], acc[i][2], acc[i][3]);
            float4 o1 = make_float4(acc[i][4], acc[i][5], acc[i][6], acc[i][7]);
            *(float4*)(C + (size_t)row * HID + c0) = o0;
            *(float4*)(C + (size_t)row * HID + c0 + 4) = o1;
        }
    }
}

// ---------------- a_s[n,h] for BOTH scales (warp per row) ----------------------
__global__ void k_as2(const float* __restrict__ hsl, const float* __restrict__ hsg,
                      const float* __restrict__ attl, const float* __restrict__ attg,
                      float* __restrict__ outl, float* __restrict__ outg) {
    int w = (blockIdx.x * blockDim.x + threadIdx.x) >> 5;
    if (w >= NN) return;
    int l = threadIdx.x & 31;
    float4 hl = *(const float4*)(hsl + (size_t)w * HID + l * 4);
    float4 al = *(const float4*)(attl + l * 4);
    float4 hg = *(const float4*)(hsg + (size_t)w * HID + l * 4);
    float4 ag = *(const float4*)(attg + l * 4);
    float pl = hl.x * al.x + hl.y * al.y + hl.z * al.z + hl.w * al.w;
    float pg = hg.x * ag.x + hg.y * ag.y + hg.z * ag.z + hg.w * ag.w;
#pragma unroll
    for (int off = 1; off < 8; off <<= 1) {
        pl += __shfl_xor_sync(0xffffffffu, pl, off);
        pg += __shfl_xor_sync(0xffffffffu, pg, off);
    }
    if ((l & 7) == 0) {
        outl[w * 4 + (l >> 3)] = pl;
        outg[w * 4 + (l >> 3)] = pg;
    }
}

// ---------------- a_d[n,h] for BOTH scales (warp per row) ----------------------
__global__ void k_ad2(const float* __restrict__ x,
                      const float* __restrict__ Vdl, const float* __restrict__ Vdg,
                      float* __restrict__ outl, float* __restrict__ outg) {
    int w = (blockIdx.x * blockDim.x + threadIdx.x) >> 5;
    if (w >= NN) return;
    int l = threadIdx.x & 31;
    float4 xv = *(const float4*)(x + (size_t)w * HID + l * 4);
    float l0 = 0.f, l1 = 0.f, l2 = 0.f, l3 = 0.f;
    float q0 = 0.f, q1 = 0.f, q2 = 0.f, q3 = 0.f;
    float xk[4] = {xv.x, xv.y, xv.z, xv.w};
#pragma unroll
    for (int j = 0; j < 4; j++) {
        float4 v = *(const float4*)(Vdl + (4 * l + j) * 4);
        l0 += xk[j] * v.x; l1 += xk[j] * v.y; l2 += xk[j] * v.z; l3 += xk[j] * v.w;
        float4 u = *(const float4*)(Vdg + (4 * l + j) * 4);
        q0 += xk[j] * u.x; q1 += xk[j] * u.y; q2 += xk[j] * u.z; q3 += xk[j] * u.w;
    }
#pragma unroll
    for (int off = 16; off; off >>= 1) {
        l0 += __shfl_xor_sync(0xffffffffu, l0, off);
        l1 += __shfl_xor_sync(0xffffffffu, l1, off);
        l2 += __shfl_xor_sync(0xffffffffu, l2, off);
        l3 += __shfl_xor_sync(0xffffffffu, l3, off);
        q0 += __shfl_xor_sync(0xffffffffu, q0, off);
        q1 += __shfl_xor_sync(0xffffffffu, q1, off);
        q2 += __shfl_xor_sync(0xffffffffu, q2, off);
        q3 += __shfl_xor_sync(0xffffffffu, q3, off);
    }
    if (l == 0) {
        *(float4*)(outl + w * 4) = make_float4(l0, l1, l2, l3);
        *(float4*)(outg + w * 4) = make_float4(q0, q1, q2, q3);
    }
}

// ---------------- CSR build ----------------------------------------------------
__global__ void k_zero(int* __restrict__ cnt) {
    int i = blockIdx.x * blockDim.x + threadIdx.x;
    if (i < NN) cnt[i] = 0;
}

__global__ void k_hist(const int* __restrict__ dst, int nedge, int total, int* __restrict__ cnt) {
    int i = blockIdx.x * blockDim.x + threadIdx.x;
    if (i >= total) return;
    int d = (i < nedge) ? dst[i] : (i - nedge);
    atomicAdd(&cnt[d], 1);
}

__global__ void k_scan(const int* __restrict__ cnt, int* __restrict__ rowptr,
                       int* __restrict__ cursor) {
    __shared__ int wsum[32];
    int tid = threadIdx.x;
    int lane = tid & 31, wid = tid >> 5;
    int running = 0;
    const int CH = 4096;
    for (int base = 0; base < NN; base += CH) {
        int i0 = base + tid * 4;
        int v0 = 0, v1 = 0, v2 = 0, v3 = 0;
        if (i0 + 3 < NN) {
            int4 t = *(const int4*)(cnt + i0);
            v0 = t.x; v1 = t.y; v2 = t.z; v3 = t.w;
        } else {
            if (i0 < NN) v0 = cnt[i0];
            if (i0 + 1 < NN) v1 = cnt[i0 + 1];
            if (i0 + 2 < NN) v2 = cnt[i0 + 2];
            if (i0 + 3 < NN) v3 = cnt[i0 + 3];
        }
        int s = v0 + v1 + v2 + v3;
        int sc = s;
#pragma unroll
        for (int off = 1; off < 32; off <<= 1) {
            int t = __shfl_up_sync(0xffffffffu, sc, off);
            if (lane >= off) sc += t;
        }
        if (lane == 31) wsum[wid] = sc;
        __syncthreads();
        if (wid == 0) {
            int x = wsum[lane];
#pragma unroll
            for (int off = 1; off < 32; off <<= 1) {
                int t = __shfl_up_sync(0xffffffffu, x, off);
                if (lane >= off) x += t;
            }
            wsum[lane] = x;
        }
        __syncthreads();
        int warpoff = (wid > 0) ? wsum[wid - 1] : 0;
        int chunk_total = wsum[31];
        int p = running + warpoff + (sc - s);
        if (i0 < NN) { rowptr[i0] = p; cursor[i0] = p; } p += v0;
        if (i0 + 1 < NN) { rowptr[i0 + 1] = p; cursor[i0 + 1] = p; } p += v1;
        if (i0 + 2 < NN) { rowptr[i0 + 2] = p; cursor[i0 + 2] = p; } p += v2;
        if (i0 + 3 < NN) { rowptr[i0 + 3] = p; cursor[i0 + 3] = p; }
        running += chunk_total;
        __syncthreads();
    }
    if (tid == 0) rowptr[NN] = running;
}

__global__ void k_scatter(const int* __restrict__ src, const int* __restrict__ dst,
                          int nedge, int total, int* __restrict__ cursor,
                          int* __restrict__ srcs) {
    int i = blockIdx.x * blockDim.x + threadIdx.x;
    if (i >= total) return;
    int s, d;
    if (i < nedge) { s = src[i]; d = dst[i]; }
    else { s = d = i - nedge; }
    int pos = atomicAdd(&cursor[d], 1);
    srcs[pos] = s;
}

// ---------------- warp-per-dst softmax aggregation, both scales ----------------
__global__ void k_agg(const float* __restrict__ hsl, const float* __restrict__ hsg,
                      const float* __restrict__ asl, const float* __restrict__ asg,
                      const float* __restrict__ adl, const float* __restrict__ adg,
                      const int* __restrict__ rowptr, const int* __restrict__ srcs,
                      float* __restrict__ outl, float* __restrict__ outg) {
    int warp = (blockIdx.x * blockDim.x + threadIdx.x) >> 5;
    if (warp >= NN) return;
    int lane = threadIdx.x & 31;
    float4 vadl = *(const float4*)(adl + warp * 4);
    float4 vadg = *(const float4*)(adg + warp * 4);
    int beg = rowptr[warp], end = rowptr[warp + 1];

    const float NEG = -3.0e38f;
    float ml0 = NEG, ml1 = NEG, ml2 = NEG, ml3 = NEG;
    float mg0 = NEG, mg1 = NEG, mg2 = NEG, mg3 = NEG;
    for (int e = beg + lane; e < end; e += 32) {
        int s = srcs[e];
        float4 al = *(const float4*)(asl + s * 4);
        float4 ag = *(const float4*)(asg + s * 4);
        ml0 = fmaxf(ml0, lrelu(al.x + vadl.x, 0.2f));
        ml1 = fmaxf(ml1, lrelu(al.y + vadl.y, 0.2f));
        ml2 = fmaxf(ml2, lrelu(al.z + vadl.z, 0.2f));
        ml3 = fmaxf(ml3, lrelu(al.w + vadl.w, 0.2f));
        mg0 = fmaxf(mg0, lrelu(ag.x + vadg.x, 0.3f));
        mg1 = fmaxf(mg1, lrelu(ag.y + vadg.y, 0.3f));
        mg2 = fmaxf(mg2, lrelu(ag.z + vadg.z, 0.3f));
        mg3 = fmaxf(mg3, lrelu(ag.w + vadg.w, 0.3f));
    }
#pragma unroll
    for (int off = 16; off; off >>= 1) {
        ml0 = fmaxf(ml0, __shfl_xor_sync(0xffffffffu, ml0, off));
        ml1 = fmaxf(ml1, __shfl_xor_sync(0xffffffffu, ml1, off));
        ml2 = fmaxf(ml2, __shfl_xor_sync(0xffffffffu, ml2, off));
        ml3 = fmaxf(ml3, __shfl_xor_sync(0xffffffffu, ml3, off));
        mg0 = fmaxf(mg0, __shfl_xor_sync(0xffffffffu, mg0, off));
        mg1 = fmaxf(mg1, __shfl_xor_sync(0xffffffffu, mg1, off));
        mg2 = fmaxf(mg2, __shfl_xor_sync(0xffffffffu, mg2, off));
        mg3 = fmaxf(mg3, __shfl_xor_sync(0xffffffffu, mg3, off));
    }
    float dl0 = 0.f, dl1 = 0.f, dl2 = 0.f, dl3 = 0.f;
    float dg0 = 0.f, dg1 = 0.f, dg2 = 0.f, dg3 = 0.f;
    for (int e = beg + lane; e < end; e += 32) {
        int s = srcs[e];
        float4 al = *(const float4*)(asl + s * 4);
        float4 ag = *(const float4*)(asg + s * 4);
        dl0 += __expf(lrelu(al.x + vadl.x, 0.2f) - ml0);
        dl1 += __expf(lrelu(al.y + vadl.y, 0.2f) - ml1);
        dl2 += __expf(lrelu(al.z + vadl.z, 0.2f) - ml2);
        dl3 += __expf(lrelu(al.w + vadl.w, 0.2f) - ml3);
        dg0 += __expf(lrelu(ag.x + vadg.x, 0.3f) - mg0);
        dg1 += __expf(lrelu(ag.y + vadg.y, 0.3f) - mg1);
        dg2 += __expf(lrelu(ag.z + vadg.z, 0.3f) - mg2);
        dg3 += __expf(lrelu(ag.w + vadg.w, 0.3f) - mg3);
    }
#pragma unroll
    for (int off = 16; off; off >>= 1) {
        dl0 += __shfl_xor_sync(0xffffffffu, dl0, off);
        dl1 += __shfl_xor_sync(0xffffffffu, dl1, off);
        dl2 += __shfl_xor_sync(0xffffffffu, dl2, off);
        dl3 += __shfl_xor_sync(0xffffffffu, dl3, off);
        dg0 += __shfl_xor_sync(0xffffffffu, dg0, off);
        dg1 += __shfl_xor_sync(0xffffffffu, dg1, off);
        dg2 += __shfl_xor_sync(0xffffffffu, dg2, off);
        dg3 += __shfl_xor_sync(0xffffffffu, dg3, off);
    }
    float rl0 = 1.f / (dl0 + 1e-16f), rl1 = 1.f / (dl1 + 1e-16f);
    float rl2 = 1.f / (dl2 + 1e-16f), rl3 = 1.f / (dl3 + 1e-16f);
    float rg0 = 1.f / (dg0 + 1e-16f), rg1 = 1.f / (dg1 + 1e-16f);
    float rg2 = 1.f / (dg2 + 1e-16f), rg3 = 1.f / (dg3 + 1e-16f);

    int myh = lane >> 3;
    float m_l = sel4(myh, ml0, ml1, ml2, ml3);
    float r_l = sel4(myh, rl0, rl1, rl2, rl3);
    float a_dl = sel4(myh, vadl.x, vadl.y, vadl.z, vadl.w);
    float m_g = sel4(myh, mg0, mg1, mg2, mg3);
    float r_g = sel4(myh, rg0, rg1, rg2, rg3);
    float a_dg = sel4(myh, vadg.x, vadg.y, vadg.z, vadg.w);

    float4 accl = make_float4(0.f, 0.f, 0.f, 0.f);
    float4 accg = make_float4(0.f, 0.f, 0.f, 0.f);
    int col = lane * 4;
    for (int e = beg; e < end; e++) {
        int s = srcs[e];
        float4 al = *(const float4*)(asl + s * 4);
        float4 ag = *(const float4*)(asg + s * 4);
        float as_l = sel4(myh, al.x, al.y, al.z, al.w);
        float as_g = sel4(myh, ag.x, ag.y, ag.z, ag.w);
        float wl = __expf(lrelu(as_l + a_dl, 0.2f) - m_l) * r_l;
        float wg = __expf(lrelu(as_g + a_dg, 0.3f) - m_g) * r_g;
        float4 hl = *(const float4*)(hsl + (size_t)s * HID + col);
        float4 hg = *(const float4*)(hsg + (size_t)s * HID + col);
        accl.x += wl * hl.x; accl.y += wl * hl.y; accl.z += wl * hl.z; accl.w += wl * hl.w;
        accg.x += wg * hg.x; accg.y += wg * hg.y; accg.z += wg * hg.z; accg.w += wg * hg.w;
    }
    *(float4*)(outl + (size_t)warp * HID + col) = accl;
    *(float4*)(outg + (size_t)warp * HID + col) = accg;
}

// ---------------- fused gate + blend + output GEMM -----------------------------
__global__ __launch_bounds__(256) void k_fuse(
    const float* __restrict__ aggA_l, const float* __restrict__ aggA_g,
    const float* __restrict__ aggB_l, const float* __restrict__ aggB_g,
    const float* __restrict__ biasA_l, const float* __restrict__ biasA_g,
    const float* __restrict__ biasB_l, const float* __restrict__ biasB_g,
    const float* __restrict__ relgates,
    const float* __restrict__ gW, const float* __restrict__ gb,
    const float* __restrict__ oW, float* __restrict__ out) {
    extern __shared__ float sm[];
    float* As = sm;                 // 32 x 260 (cols 0..255 = [loc, glb])
    float* Bs = sm + 32 * 260;      // 256 x 128
    int tid = threadIdx.x;
    int tx = tid & 15, ty = tid >> 4;
    int row0 = blockIdx.x * 32;

    float w0 = 1.f, w1 = 0.f;
    if (relgates) {
        float g0 = relgates[0], g1 = relgates[1];
        float m = fmaxf(g0, g1);
        float e0 = __expf(g0 - m), e1 = __expf(g1 - m);
        float inv = 1.f / (e0 + e1);
        w0 = e0 * inv; w1 = e1 * inv;
    }

    // build A tile = [loc | glb] incl. biases
#pragma unroll
    for (int i = 0; i < 8; i++) {
        int fi = tid + i * 256;
        int r = fi >> 6, q = fi & 63;
        int c = q * 4;
        int grow = row0 + r;
        float4 v;
        if (c < 128) {
            float4 a = *(const float4*)(aggA_l + (size_t)grow * HID + c);
            float4 b = *(const float4*)(biasA_l + c);
            v.x = w0 * (a.x + b.x); v.y = w0 * (a.y + b.y);
            v.z = w0 * (a.z + b.z); v.w = w0 * (a.w + b.w);
            if (aggB_l) {
                float4 a2 = *(const float4*)(aggB_l + (size_t)grow * HID + c);
                float4 b2 = *(const float4*)(biasB_l + c);
                v.x += w1 * (a2.x + b2.x); v.y += w1 * (a2.y + b2.y);
                v.z += w1 * (a2.z + b2.z); v.w += w1 * (a2.w + b2.w);
            }
        } else {
            int c2 = c - 128;
            float4 a = *(const float4*)(aggA_g + (size_t)grow * HID + c2);
            float4 b = *(const float4*)(biasA_g + c2);
            v.x = w0 * (a.x + b.x); v.y = w0 * (a.y + b.y);
            v.z = w0 * (a.z + b.z); v.w = w0 * (a.w + b.w);
            if (aggB_g) {
                float4 a2 = *(const float4*)(aggB_g + (size_t)grow * HID + c2);
                float4 b2 = *(const float4*)(biasB_g + c2);
                v.x += w1 * (a2.x + b2.x); v.y += w1 * (a2.y + b2.y);
                v.z += w1 * (a2.z + b2.z); v.w += w1 * (a2.w + b2.w);
            }
        }
        *(float4*)(As + r * 260 + c) = v;
    }
    // load gate_W (256x128)
#pragma unroll
    for (int i = 0; i < 32; i++) {
        int fi = tid + i * 256;
        int r = fi >> 5, q = fi & 31;
        *(float4*)(Bs + r * 128 + q * 4) = *(const float4*)(gW + r * 128 + q * 4);
    }
    __syncthreads();

    // stage 1: gate logits = A[32x256] @ gW[256x128]
    float acc[2][8];
#pragma unroll
    for (int i = 0; i < 2; i++)
#pragma unroll
        for (int j = 0; j < 8; j++) acc[i][j] = 0.f;
    int ra = ty * 2, c0 = tx * 8;
#pragma unroll 8
    for (int k = 0; k < 256; k++) {
        float a0 = As[(ra + 0) * 260 + k];
        float a1 = As[(ra + 1) * 260 + k];
        float4 b0 = *(float4*)(Bs + k * 128 + c0);
        float4 b1 = *(float4*)(Bs + k * 128 + c0 + 4);
        float bb[8] = {b0.x, b0.y, b0.z, b0.w, b1.x, b1.y, b1.z, b1.w};
#pragma unroll
        for (int j = 0; j < 8; j++) { acc[0][j] += a0 * bb[j]; acc[1][j] += a1 * bb[j]; }
    }
    // gate + blend (to regs)
    float blend[2][8];
#pragma unroll
    for (int i = 0; i < 2; i++)
#pragma unroll
        for (int j = 0; j < 8; j++) {
            int col = c0 + j;
            float g = 1.f / (1.f + __expf(-(acc[i][j] + __ldg(gb + col))));
            float lo = As[(ra + i) * 260 + col];
            float gl = As[(ra + i) * 260 + 128 + col];
            blend[i][j] = g * lo + (1.f - g) * gl;
        }
    __syncthreads();
    // write blended into As cols 0..127; load out_W into Bs
#pragma unroll
    for (int i = 0; i < 2; i++)
#pragma unroll
        for (int j = 0; j < 8; j++) As[(ra + i) * 260 + c0 + j] = blend[i][j];
#pragma unroll
    for (int i = 0; i < 16; i++) {
        int fi = tid + i * 256;
        int r = fi >> 5, q = fi & 31;
        *(float4*)(Bs + r * 128 + q * 4) = *(const float4*)(oW + r * 128 + q * 4);
    }
    __syncthreads();

    // stage 2: out = blended[32x128] @ oW[128x128]
    float acc2[2][8];
#pragma unroll
    for (int i = 0; i < 2; i++)
#pragma unroll
        for (int j = 0; j < 8; j++) acc2[i][j] = 0.f;
#pragma unroll 8
    for (int k = 0; k < 128; k++) {
        float a0 = As[(ra + 0) * 260 + k];
        float a1 = As[(ra + 1) * 260 + k];
        float4 b0 = *(float4*)(Bs + k * 128 + c0);
        float4 b1 = *(float4*)(Bs + k * 128 + c0 + 4);
        float bb[8] = {b0.x, b0.y, b0.z, b0.w, b1.x, b1.y, b1.z, b1.w};
#pragma unroll
        for (int j = 0; j < 8; j++) { acc2[0][j] += a0 * bb[j]; acc2[1][j] += a1 * bb[j]; }
    }
#pragma unroll
    for (int i = 0; i < 2; i++) {
        int row = row0 + ra + i;
        float4 o0 = make_float4(acc2[i][0], acc2[i][1], acc2[i][2], acc2[i][3]);
        float4 o1 = make_float4(acc2[i][4], acc2[i][5], acc2[i][6], acc2[i][7]);
        *(float4*)(out + (size_t)row * HID + c0) = o0;
        *(float4*)(out + (size_t)row * HID + c0 + 4) = o1;
    }
}

// ---------------- host orchestration -------------------------------------------
extern "C" void kernel_launch(void* const* d_in, const int* in_sizes, int n_in,
                              void* d_out, int out_size) {
    const float* x_user   = (const float*)d_in[0];
    const float* x_item   = (const float*)d_in[1];
    const float* W_src_l  = (const float*)d_in[2];
    const float* W_dst_l  = (const float*)d_in[3];
    const float* att_s_l  = (const float*)d_in[4];
    const float* att_d_l  = (const float*)d_in[5];
    const float* bias_l   = (const float*)d_in[6];
    const float* W_src_g  = (const float*)d_in[7];
    const float* W_dst_g  = (const float*)d_in[8];
    const float* att_s_g  = (const float*)d_in[9];
    const float* att_d_g  = (const float*)d_in[10];
    const float* bias_g   = (const float*)d_in[11];
    const float* gate_W   = (const float*)d_in[12];
    const float* gate_b   = (const float*)d_in[13];
    const float* out_W    = (const float*)d_in[14];
    const float* relgates = (const float*)d_in[15];
    const int*   ei_buys  = (const int*)d_in[16];
    const int*   ei_rev   = (const int*)d_in[17];
    const int*   ei_fol   = (const int*)d_in[18];
    float* outp = (float*)d_out;

    float *p_hsl, *p_hsg, *p_asl, *p_asg, *p_adl, *p_adg, *p_agg, *p_vd;
    int *p_cnt, *p_rowptr, *p_cursor, *p_srcs;
    cudaGetSymbolAddress((void**)&p_hsl, g_hs_l);
    cudaGetSymbolAddress((void**)&p_hsg, g_hs_g);
    cudaGetSymbolAddress((void**)&p_asl, g_as_l);
    cudaGetSymbolAddress((void**)&p_asg, g_as_g);
    cudaGetSymbolAddress((void**)&p_adl, g_ad_l);
    cudaGetSymbolAddress((void**)&p_adg, g_ad_g);
    cudaGetSymbolAddress((void**)&p_agg, g_agg);
    cudaGetSymbolAddress((void**)&p_vd, g_vd);
    cudaGetSymbolAddress((void**)&p_cnt, g_cnt);
    cudaGetSymbolAddress((void**)&p_rowptr, g_rowptr);
    cudaGetSymbolAddress((void**)&p_cursor, g_cursor);
    cudaGetSymbolAddress((void**)&p_srcs, g_srcs);

    cudaFuncSetAttribute(k_gemm, cudaFuncAttributeMaxDynamicSharedMemorySize, SMEM_GEMM);
    cudaFuncSetAttribute(k_fuse, cudaFuncAttributeMaxDynamicSharedMemorySize, SMEM_FUSE);

    k_compute_vd<<<12, 128>>>(W_dst_l, att_d_l, W_dst_g, att_d_g);

    const float* xs_arr[3] = {x_user, x_item, x_user};
    const float* xd_arr[3] = {x_item, x_user, x_user};
    const int*   ei_arr[3] = {ei_buys, ei_rev, ei_fol};
    const int    sl_arr[3] = {0, 0, 1};

    int gemm_blocks = (NN + 63) / 64;
    int warp_blocks = (NN + 7) / 8;

    for (int r = 0; r < 3; r++) {
        const float* xs = xs_arr[r];
        const float* xd = xd_arr[r];
        const int* src = ei_arr[r];
        const int* dst = ei_arr[r] + EE;
        int tot = EE + (sl_arr[r] ? NN : 0);

        k_gemm<<<gemm_blocks, 256, SMEM_GEMM>>>(xs, W_src_l + r * HID * HID, p_hsl, NN);
        k_gemm<<<gemm_blocks, 256, SMEM_GEMM>>>(xs, W_src_g + r * HID * HID, p_hsg, NN);
        k_as2<<<warp_blocks, 256>>>(p_hsl, p_hsg, att_s_l + r * HID, att_s_g + r * HID,
                                    p_asl, p_asg);
        k_ad2<<<warp_blocks, 256>>>(xd, p_vd + (r * 2 + 0) * HID * 4,
                                    p_vd + (r * 2 + 1) * HID * 4, p_adl, p_adg);

        k_zero<<<(NN + 255) / 256, 256>>>(p_cnt);
        k_hist<<<(tot + 255) / 256, 256>>>(dst, EE, tot, p_cnt);
        k_scan<<<1, 1024>>>(p_cnt, p_rowptr, p_cursor);
        k_scatter<<<(tot + 255) / 256, 256>>>(src, dst, EE, tot, p_cursor, p_srcs);

        k_agg<<<warp_blocks, 256>>>(p_hsl, p_hsg, p_asl, p_asg, p_adl, p_adg,
                                    p_rowptr, p_srcs,
                                    p_agg + (size_t)(r * 2 + 0) * NN * HID,
                                    p_agg + (size_t)(r * 2 + 1) * NN * HID);
    }

    // user: rel1 (rev) with gw[0], rel2 (follows) with gw[1]
    k_fuse<<<NN / 32, 256, SMEM_FUSE>>>(
        p_agg + (size_t)2 * NN * HID, p_agg + (size_t)3 * NN * HID,
        p_agg + (size_t)4 * NN * HID, p_agg + (size_t)5 * NN * HID,
        bias_l + 1 * HID, bias_g + 1 * HID, bias_l + 2 * HID, bias_g + 2 * HID,
        relgates, gate_W, gate_b, out_W, outp);
    // item: rel0 (buys) only
    k_fuse<<<NN / 32, 256, SMEM_FUSE>>>(
        p_agg + (size_t)0 * NN * HID, p_agg + (size_t)1 * NN * HID,
        nullptr, nullptr,
        bias_l, bias_g, nullptr, nullptr,
        nullptr, gate_W + 256 * 128, gate_b + 128, out_W + 128 * 128,
        outp + (size_t)NN * HID);
}

// round 3
// speedup vs baseline: 1.1617x; 1.1617x over previous
#include <cuda_runtime.h>
#include <math.h>

#define NN 100000
#define EE 1000000
#define HID 128

// ---------------- device scratch ------------------------------------------------
__device__ float g_buf_u[(size_t)NN * 512];   // hs for rel0(l,g), rel2(l,g)
__device__ float g_buf_i[(size_t)NN * 256];   // hs for rel1(l,g)
__device__ float g_agg[(size_t)6 * NN * HID]; // [rel*2+scale][NN][128]
__device__ float g_v[24 * HID * 4];           // 0-11: vd combos, 12-23: vs combos
__device__ float g_asl[3 * NN * 4];
__device__ float g_asg[3 * NN * 4];
__device__ float g_adl[3 * NN * 4];
__device__ float g_adg[3 * NN * 4];
__device__ int   g_cnt[3 * NN];
__device__ int   g_rowptr[3 * (NN + 1)];
__device__ int   g_cursor[3 * NN];
__device__ int   g_srcs[3 * (EE + NN)];

#define SMEM_MMA ((128 * 132 * 2) * 4)
#define SMEM_FUSE ((32 * 260 + 256 * 128) * 4)

__device__ __forceinline__ float lrelu(float x, float s) { return x > 0.f ? x : s * x; }

// ---------------- v vectors: v[k,h] = sum_c W[k, h*32+c] * att[h,c] -------------
__global__ void k_compute_v(const float* __restrict__ Wdl, const float* __restrict__ attdl,
                            const float* __restrict__ Wdg, const float* __restrict__ attdg,
                            const float* __restrict__ Wsl, const float* __restrict__ attsl,
                            const float* __restrict__ Wsg, const float* __restrict__ attsg) {
    int combo = blockIdx.x;          // 0-11 dst, 12-23 src
    int k = threadIdx.x;             // 0..127
    int cc = combo % 12;
    int r = cc >> 1, s = cc & 1;
    const float* W;
    const float* att;
    if (combo < 12) { W = (s ? Wdg : Wdl) + r * HID * HID; att = (s ? attdg : attdl) + r * HID; }
    else            { W = (s ? Wsg : Wsl) + r * HID * HID; att = (s ? attsg : attsl) + r * HID; }
#pragma unroll
    for (int h = 0; h < 4; h++) {
        float sum = 0.f;
#pragma unroll
        for (int c = 0; c < 32; c++)
            sum += W[k * HID + h * 32 + c] * att[h * 32 + c];
        g_v[combo * HID * 4 + k * 4 + h] = sum;
    }
}

// ---------------- scores: out[n,h] = x[n,:] @ V[:,h], both scales ---------------
__global__ void k_scores(const float* __restrict__ x,
                         const float* __restrict__ Vl, const float* __restrict__ Vg,
                         float* __restrict__ outl, float* __restrict__ outg) {
    int w = (blockIdx.x * blockDim.x + threadIdx.x) >> 5;
    if (w >= NN) return;
    int l = threadIdx.x & 31;
    float4 xv = *(const float4*)(x + (size_t)w * HID + l * 4);
    float l0 = 0.f, l1 = 0.f, l2 = 0.f, l3 = 0.f;
    float q0 = 0.f, q1 = 0.f, q2 = 0.f, q3 = 0.f;
    float xk[4] = {xv.x, xv.y, xv.z, xv.w};
#pragma unroll
    for (int j = 0; j < 4; j++) {
        float4 v = *(const float4*)(Vl + (4 * l + j) * 4);
        l0 += xk[j] * v.x; l1 += xk[j] * v.y; l2 += xk[j] * v.z; l3 += xk[j] * v.w;
        float4 u = *(const float4*)(Vg + (4 * l + j) * 4);
        q0 += xk[j] * u.x; q1 += xk[j] * u.y; q2 += xk[j] * u.z; q3 += xk[j] * u.w;
    }
#pragma unroll
    for (int off = 16; off; off >>= 1) {
        l0 += __shfl_xor_sync(0xffffffffu, l0, off);
        l1 += __shfl_xor_sync(0xffffffffu, l1, off);
        l2 += __shfl_xor_sync(0xffffffffu, l2, off);
        l3 += __shfl_xor_sync(0xffffffffu, l3, off);
        q0 += __shfl_xor_sync(0xffffffffu, q0, off);
        q1 += __shfl_xor_sync(0xffffffffu, q1, off);
        q2 += __shfl_xor_sync(0xffffffffu, q2, off);
        q3 += __shfl_xor_sync(0xffffffffu, q3, off);
    }
    if (l == 0) {
        *(float4*)(outl + w * 4) = make_float4(l0, l1, l2, l3);
        *(float4*)(outg + w * 4) = make_float4(q0, q1, q2, q3);
    }
}

// ---------------- split-tf32 tensor-core GEMM: C = A[M,128] @ W[128,128] --------
struct WPtrs { const float* w[4]; };

__device__ __forceinline__ void fsplit(float v, float& hi, float& lo) {
    hi = __uint_as_float(__float_as_uint(v) & 0xFFFFE000u);
    lo = v - hi;
}

__device__ __forceinline__ void mma8(float* d, const float* a, const float* b) {
    asm volatile(
        "mma.sync.aligned.m16n8k8.row.col.f32.tf32.tf32.f32 "
        "{%0,%1,%2,%3}, {%4,%5,%6,%7}, {%8,%9}, {%0,%1,%2,%3};\n"
        : "+f"(d[0]), "+f"(d[1]), "+f"(d[2]), "+f"(d[3])
        : "r"(__float_as_uint(a[0])), "r"(__float_as_uint(a[1])),
          "r"(__float_as_uint(a[2])), "r"(__float_as_uint(a[3])),
          "r"(__float_as_uint(b[0])), "r"(__float_as_uint(b[1])));
}

__global__ __launch_bounds__(256) void k_gemm_tf32(
    const float* __restrict__ A, int M, WPtrs wp,
    float* __restrict__ C, int S) {
    extern __shared__ float sm[];
    float* As = sm;                 // [128][132]
    float* Bs = sm + 128 * 132;     // [128][132]
    int tid = threadIdx.x;
    int m0 = blockIdx.x * 128;
    const float* W = wp.w[blockIdx.y];
    int cbase = blockIdx.y * 128;

    // load A tile (guarded) and W tile
#pragma unroll
    for (int i = 0; i < 16; i++) {
        int f = tid + i * 256;
        int r = f >> 5, q = (f & 31) * 4;
        float4 v = make_float4(0.f, 0.f, 0.f, 0.f);
        if (m0 + r < M) v = *(const float4*)(A + (size_t)(m0 + r) * HID + q);
        *(float4*)(As + r * 132 + q) = v;
        *(float4*)(Bs + r * 132 + q) = *(const float4*)(W + r * HID + q);
    }
    __syncthreads();

    int warp = tid >> 5;
    int wm = warp & 3;              // rows wm*32
    int wn = warp >> 2;             // cols wn*64
    int lane = tid & 31;
    int g = lane >> 2, tr = lane & 3;

    float acc[2][8][4];
#pragma unroll
    for (int mt = 0; mt < 2; mt++)
#pragma unroll
        for (int nt = 0; nt < 8; nt++)
#pragma unroll
            for (int q = 0; q < 4; q++) acc[mt][nt][q] = 0.f;

#pragma unroll
    for (int ks = 0; ks < 16; ks++) {
        int k0 = ks * 8;
        float ah[2][4], al[2][4];
#pragma unroll
        for (int mt = 0; mt < 2; mt++) {
            int rb = wm * 32 + mt * 16;
            float v0 = As[(rb + g) * 132 + k0 + tr];
            float v1 = As[(rb + 8 + g) * 132 + k0 + tr];
            float v2 = As[(rb + g) * 132 + k0 + tr + 4];
            float v3 = As[(rb + 8 + g) * 132 + k0 + tr + 4];
            fsplit(v0, ah[mt][0], al[mt][0]);
            fsplit(v1, ah[mt][1], al[mt][1]);
            fsplit(v2, ah[mt][2], al[mt][2]);
            fsplit(v3, ah[mt][3], al[mt][3]);
        }
        float bh[8][2], bl[8][2];
#pragma unroll
        for (int nt = 0; nt < 8; nt++) {
            int n = wn * 64 + nt * 8 + g;
            float u0 = Bs[(k0 + tr) * 132 + n];
            float u1 = Bs[(k0 + tr + 4) * 132 + n];
            fsplit(u0, bh[nt][0], bl[nt][0]);
            fsplit(u1, bh[nt][1], bl[nt][1]);
        }
#pragma unroll
        for (int mt = 0; mt < 2; mt++)
#pragma unroll
            for (int nt = 0; nt < 8; nt++) {
                mma8(acc[mt][nt], ah[mt], bh[nt]);
                mma8(acc[mt][nt], ah[mt], bl[nt]);
                mma8(acc[mt][nt], al[mt], bh[nt]);
            }
    }

#pragma unroll
    for (int mt = 0; mt < 2; mt++)
#pragma unroll
        for (int nt = 0; nt < 8; nt++) {
            int r0 = m0 + wm * 32 + mt * 16 + g;
            int cc = cbase + wn * 64 + nt * 8 + 2 * tr;
            if (r0 < M)
                *(float2*)(C + (size_t)r0 * S + cc) = make_float2(acc[mt][nt][0], acc[mt][nt][1]);
            if (r0 + 8 < M)
                *(float2*)(C + (size_t)(r0 + 8) * S + cc) = make_float2(acc[mt][nt][2], acc[mt][nt][3]);
        }
}

// ---------------- CSR build (all 3 relations) -----------------------------------
struct EdgePtrs { const int* src[3]; const int* dst[3]; int tot[3]; };

__global__ void k_zero(int* __restrict__ cnt) {
    int i = blockIdx.x * blockDim.x + threadIdx.x;
    if (i < 3 * NN) cnt[i] = 0;
}

__global__ void k_hist(EdgePtrs E, int* __restrict__ cnt) {
    int rel = blockIdx.y;
    int i = blockIdx.x * blockDim.x + threadIdx.x;
    if (i >= E.tot[rel]) return;
    int d = (i < EE) ? E.dst[rel][i] : (i - EE);
    atomicAdd(&cnt[rel * NN + d], 1);
}

__global__ void k_scan(const int* __restrict__ cnt_all, int* __restrict__ rowptr_all,
                       int* __restrict__ cursor_all) {
    __shared__ int wsum[32];
    int rel = blockIdx.x;
    const int* cnt = cnt_all + rel * NN;
    int* rowptr = rowptr_all + rel * (NN + 1);
    int* cursor = cursor_all + rel * NN;
    int tid = threadIdx.x;
    int lane = tid & 31, wid = tid >> 5;
    int running = 0;
    const int CH = 4096;
    for (int base = 0; base < NN; base += CH) {
        int i0 = base + tid * 4;
        int v0 = 0, v1 = 0, v2 = 0, v3 = 0;
        if (i0 + 3 < NN) {
            int4 t = *(const int4*)(cnt + i0);
            v0 = t.x; v1 = t.y; v2 = t.z; v3 = t.w;
        } else {
            if (i0 < NN) v0 = cnt[i0];
            if (i0 + 1 < NN) v1 = cnt[i0 + 1];
            if (i0 + 2 < NN) v2 = cnt[i0 + 2];
            if (i0 + 3 < NN) v3 = cnt[i0 + 3];
        }
        int s = v0 + v1 + v2 + v3;
        int sc = s;
#pragma unroll
        for (int off = 1; off < 32; off <<= 1) {
            int t = __shfl_up_sync(0xffffffffu, sc, off);
            if (lane >= off) sc += t;
        }
        if (lane == 31) wsum[wid] = sc;
        __syncthreads();
        if (wid == 0) {
            int x = wsum[lane];
#pragma unroll
            for (int off = 1; off < 32; off <<= 1) {
                int t = __shfl_up_sync(0xffffffffu, x, off);
                if (lane >= off) x += t;
            }
            wsum[lane] = x;
        }
        __syncthreads();
        int warpoff = (wid > 0) ? wsum[wid - 1] : 0;
        int chunk_total = wsum[31];
        int p = running + warpoff + (sc - s);
        if (i0 < NN) { rowptr[i0] = p; cursor[i0] = p; } p += v0;
        if (i0 + 1 < NN) { rowptr[i0 + 1] = p; cursor[i0 + 1] = p; } p += v1;
        if (i0 + 2 < NN) { rowptr[i0 + 2] = p; cursor[i0 + 2] = p; } p += v2;
        if (i0 + 3 < NN) { rowptr[i0 + 3] = p; cursor[i0 + 3] = p; }
        running += chunk_total;
        __syncthreads();
    }
    if (tid == 0) rowptr[NN] = running;
}

__global__ void k_scatter(EdgePtrs E, int* __restrict__ cursor_all, int* __restrict__ srcs_all) {
    int rel = blockIdx.y;
    int i = blockIdx.x * blockDim.x + threadIdx.x;
    if (i >= E.tot[rel]) return;
    int s, d;
    if (i < EE) { s = E.src[rel][i]; d = E.dst[rel][i]; }
    else { s = d = i - EE; }
    int pos = atomicAdd(&cursor_all[rel * NN + d], 1);
    srcs_all[rel * (EE + NN) + pos] = s;
}

// ---------------- single-pass softmax aggregation (all 3 relations) ------------
struct AggRel {
    const float* hsl; const float* hsg; int stride;
    const float* asl; const float* asg;
    const float* adl; const float* adg;
    const int* rowptr; const int* srcs;
    float* outl; float* outg;
};
struct AggParams { AggRel r[3]; };

__global__ void k_agg_all(AggParams P) {
    int rel = blockIdx.y;
    int node = (blockIdx.x * blockDim.x + threadIdx.x) >> 5;
    if (node >= NN) return;
    const AggRel R = P.r[rel];
    int lane = threadIdx.x & 31;
    int h = lane >> 3;
    float adl = R.adl[node * 4 + h];
    float adg = R.adg[node * 4 + h];
    int beg = R.rowptr[node], end = R.rowptr[node + 1];
    float dl = 0.f, dg = 0.f;
    float4 accl = make_float4(0.f, 0.f, 0.f, 0.f);
    float4 accg = make_float4(0.f, 0.f, 0.f, 0.f);
    int col = lane * 4;
    for (int e = beg; e < end; e++) {
        int s = R.srcs[e];
        float el = lrelu(R.asl[s * 4 + h] + adl, 0.2f);
        float eg = lrelu(R.asg[s * 4 + h] + adg, 0.3f);
        float wl = __expf(el), wg = __expf(eg);
        dl += wl; dg += wg;
        float4 hv = *(const float4*)(R.hsl + (size_t)s * R.stride + col);
        float4 gv = *(const float4*)(R.hsg + (size_t)s * R.stride + col);
        accl.x += wl * hv.x; accl.y += wl * hv.y; accl.z += wl * hv.z; accl.w += wl * hv.w;
        accg.x += wg * gv.x; accg.y += wg * gv.y; accg.z += wg * gv.z; accg.w += wg * gv.w;
    }
    float il = 1.f / (dl + 1e-16f);
    float ig = 1.f / (dg + 1e-16f);
    accl.x *= il; accl.y *= il; accl.z *= il; accl.w *= il;
    accg.x *= ig; accg.y *= ig; accg.z *= ig; accg.w *= ig;
    *(float4*)(R.outl + (size_t)node * HID + col) = accl;
    *(float4*)(R.outg + (size_t)node * HID + col) = accg;
}

// ---------------- fused gate + blend + output GEMM (unchanged from R2) ----------
__global__ __launch_bounds__(256) void k_fuse(
    const float* __restrict__ aggA_l, const float* __restrict__ aggA_g,
    const float* __restrict__ aggB_l, const float* __restrict__ aggB_g,
    const float* __restrict__ biasA_l, const float* __restrict__ biasA_g,
    const float* __restrict__ biasB_l, const float* __restrict__ biasB_g,
    const float* __restrict__ relgates,
    const float* __restrict__ gW, const float* __restrict__ gb,
    const float* __restrict__ oW, float* __restrict__ out) {
    extern __shared__ float sm[];
    float* As = sm;                 // 32 x 260
    float* Bs = sm + 32 * 260;      // 256 x 128
    int tid = threadIdx.x;
    int tx = tid & 15, ty = tid >> 4;
    int row0 = blockIdx.x * 32;

    float w0 = 1.f, w1 = 0.f;
    if (relgates) {
        float g0 = relgates[0], g1 = relgates[1];
        float m = fmaxf(g0, g1);
        float e0 = __expf(g0 - m), e1 = __expf(g1 - m);
        float inv = 1.f / (e0 + e1);
        w0 = e0 * inv; w1 = e1 * inv;
    }

#pragma unroll
    for (int i = 0; i < 8; i++) {
        int fi = tid + i * 256;
        int r = fi >> 6, q = fi & 63;
        int c = q * 4;
        int grow = row0 + r;
        float4 v;
        if (c < 128) {
            float4 a = *(const float4*)(aggA_l + (size_t)grow * HID + c);
            float4 b = *(const float4*)(biasA_l + c);
            v.x = w0 * (a.x + b.x); v.y = w0 * (a.y + b.y);
            v.z = w0 * (a.z + b.z); v.w = w0 * (a.w + b.w);
            if (aggB_l) {
                float4 a2 = *(const float4*)(aggB_l + (size_t)grow * HID + c);
                float4 b2 = *(const float4*)(biasB_l + c);
                v.x += w1 * (a2.x + b2.x); v.y += w1 * (a2.y + b2.y);
                v.z += w1 * (a2.z + b2.z); v.w += w1 * (a2.w + b2.w);
            }
        } else {
            int c2 = c - 128;
            float4 a = *(const float4*)(aggA_g + (size_t)grow * HID + c2);
            float4 b = *(const float4*)(biasA_g + c2);
            v.x = w0 * (a.x + b.x); v.y = w0 * (a.y + b.y);
            v.z = w0 * (a.z + b.z); v.w = w0 * (a.w + b.w);
            if (aggB_g) {
                float4 a2 = *(const float4*)(aggB_g + (size_t)grow * HID + c2);
                float4 b2 = *(const float4*)(biasB_g + c2);
                v.x += w1 * (a2.x + b2.x); v.y += w1 * (a2.y + b2.y);
                v.z += w1 * (a2.z + b2.z); v.w += w1 * (a2.w + b2.w);
            }
        }
        *(float4*)(As + r * 260 + c) = v;
    }
#pragma unroll
    for (int i = 0; i < 32; i++) {
        int fi = tid + i * 256;
        int r = fi >> 5, q = fi & 31;
        *(float4*)(Bs + r * 128 + q * 4) = *(const float4*)(gW + r * 128 + q * 4);
    }
    __syncthreads();

    float acc[2][8];
#pragma unroll
    for (int i = 0; i < 2; i++)
#pragma unroll
        for (int j = 0; j < 8; j++) acc[i][j] = 0.f;
    int ra = ty * 2, c0 = tx * 8;
#pragma unroll 8
    for (int k = 0; k < 256; k++) {
        float a0 = As[(ra + 0) * 260 + k];
        float a1 = As[(ra + 1) * 260 + k];
        float4 b0 = *(float4*)(Bs + k * 128 + c0);
        float4 b1 = *(float4*)(Bs + k * 128 + c0 + 4);
        float bb[8] = {b0.x, b0.y, b0.z, b0.w, b1.x, b1.y, b1.z, b1.w};
#pragma unroll
        for (int j = 0; j < 8; j++) { acc[0][j] += a0 * bb[j]; acc[1][j] += a1 * bb[j]; }
    }
    float blend[2][8];
#pragma unroll
    for (int i = 0; i < 2; i++)
#pragma unroll
        for (int j = 0; j < 8; j++) {
            int col = c0 + j;
            float g = 1.f / (1.f + __expf(-(acc[i][j] + __ldg(gb + col))));
            float lo = As[(ra + i) * 260 + col];
            float gl = As[(ra + i) * 260 + 128 + col];
            blend[i][j] = g * lo + (1.f - g) * gl;
        }
    __syncthreads();
#pragma unroll
    for (int i = 0; i < 2; i++)
#pragma unroll
        for (int j = 0; j < 8; j++) As[(ra + i) * 260 + c0 + j] = blend[i][j];
#pragma unroll
    for (int i = 0; i < 16; i++) {
        int fi = tid + i * 256;
        int r = fi >> 5, q = fi & 31;
        *(float4*)(Bs + r * 128 + q * 4) = *(const float4*)(oW + r * 128 + q * 4);
    }
    __syncthreads();

    float acc2[2][8];
#pragma unroll
    for (int i = 0; i < 2; i++)
#pragma unroll
        for (int j = 0; j < 8; j++) acc2[i][j] = 0.f;
#pragma unroll 8
    for (int k = 0; k < 128; k++) {
        float a0 = As[(ra + 0) * 260 + k];
        float a1 = As[(ra + 1) * 260 + k];
        float4 b0 = *(float4*)(Bs + k * 128 + c0);
        float4 b1 = *(float4*)(Bs + k * 128 + c0 + 4);
        float bb[8] = {b0.x, b0.y, b0.z, b0.w, b1.x, b1.y, b1.z, b1.w};
#pragma unroll
        for (int j = 0; j < 8; j++) { acc2[0][j] += a0 * bb[j]; acc2[1][j] += a1 * bb[j]; }
    }
#pragma unroll
    for (int i = 0; i < 2; i++) {
        int row = row0 + ra + i;
        float4 o0 = make_float4(acc2[i][0], acc2[i][1], acc2[i][2], acc2[i][3]);
        float4 o1 = make_float4(acc2[i][4], acc2[i][5], acc2[i][6], acc2[i][7]);
        *(float4*)(out + (size_t)row * HID + c0) = o0;
        *(float4*)(out + (size_t)row * HID + c0 + 4) = o1;
    }
}

// ---------------- host orchestration -------------------------------------------
extern "C" void kernel_launch(void* const* d_in, const int* in_sizes, int n_in,
                              void* d_out, int out_size) {
    const float* x_user   = (const float*)d_in[0];
    const float* x_item   = (const float*)d_in[1];
    const float* W_src_l  = (const float*)d_in[2];
    const float* W_dst_l  = (const float*)d_in[3];
    const float* att_s_l  = (const float*)d_in[4];
    const float* att_d_l  = (const float*)d_in[5];
    const float* bias_l   = (const float*)d_in[6];
    const float* W_src_g  = (const float*)d_in[7];
    const float* W_dst_g  = (const float*)d_in[8];
    const float* att_s_g  = (const float*)d_in[9];
    const float* att_d_g  = (const float*)d_in[10];
    const float* bias_g   = (const float*)d_in[11];
    const float* gate_W   = (const float*)d_in[12];
    const float* gate_b   = (const float*)d_in[13];
    const float* out_W    = (const float*)d_in[14];
    const float* relgates = (const float*)d_in[15];
    const int*   ei_buys  = (const int*)d_in[16];
    const int*   ei_rev   = (const int*)d_in[17];
    const int*   ei_fol   = (const int*)d_in[18];
    float* outp = (float*)d_out;

    float *p_bu, *p_bi, *p_agg, *p_v, *p_asl, *p_asg, *p_adl, *p_adg;
    int *p_cnt, *p_rowptr, *p_cursor, *p_srcs;
    cudaGetSymbolAddress((void**)&p_bu, g_buf_u);
    cudaGetSymbolAddress((void**)&p_bi, g_buf_i);
    cudaGetSymbolAddress((void**)&p_agg, g_agg);
    cudaGetSymbolAddress((void**)&p_v, g_v);
    cudaGetSymbolAddress((void**)&p_asl, g_asl);
    cudaGetSymbolAddress((void**)&p_asg, g_asg);
    cudaGetSymbolAddress((void**)&p_adl, g_adl);
    cudaGetSymbolAddress((void**)&p_adg, g_adg);
    cudaGetSymbolAddress((void**)&p_cnt, g_cnt);
    cudaGetSymbolAddress((void**)&p_rowptr, g_rowptr);
    cudaGetSymbolAddress((void**)&p_cursor, g_cursor);
    cudaGetSymbolAddress((void**)&p_srcs, g_srcs);

    cudaFuncSetAttribute(k_gemm_tf32, cudaFuncAttributeMaxDynamicSharedMemorySize, SMEM_MMA);
    cudaFuncSetAttribute(k_fuse, cudaFuncAttributeMaxDynamicSharedMemorySize, SMEM_FUSE);

    // 1) v vectors
    k_compute_v<<<24, 128>>>(W_dst_l, att_d_l, W_dst_g, att_d_g,
                             W_src_l, att_s_l, W_src_g, att_s_g);

    // 2) CSR for all relations
    EdgePtrs E;
    E.src[0] = ei_buys;      E.dst[0] = ei_buys + EE;  E.tot[0] = EE;
    E.src[1] = ei_rev;       E.dst[1] = ei_rev + EE;   E.tot[1] = EE;
    E.src[2] = ei_fol;       E.dst[2] = ei_fol + EE;   E.tot[2] = EE + NN;
    k_zero<<<(3 * NN + 255) / 256, 256>>>(p_cnt);
    dim3 hgrid((EE + NN + 255) / 256, 3);
    k_hist<<<hgrid, 256>>>(E, p_cnt);
    k_scan<<<3, 1024>>>(p_cnt, p_rowptr, p_cursor);
    k_scatter<<<hgrid, 256>>>(E, p_cursor, p_srcs);

    // 3) scores (a_s from xs, a_d from xd) per relation
    const float* xs_arr[3] = {x_user, x_item, x_user};
    const float* xd_arr[3] = {x_item, x_user, x_user};
    int warp_blocks = (NN + 7) / 8;
    for (int r = 0; r < 3; r++) {
        k_scores<<<warp_blocks, 256>>>(xs_arr[r],
                                       p_v + (12 + r * 2 + 0) * 512, p_v + (12 + r * 2 + 1) * 512,
                                       p_asl + r * NN * 4, p_asg + r * NN * 4);
        k_scores<<<warp_blocks, 256>>>(xd_arr[r],
                                       p_v + (r * 2 + 0) * 512, p_v + (r * 2 + 1) * 512,
                                       p_adl + r * NN * 4, p_adg + r * NN * 4);
    }

    // 4) feature GEMMs (tensor core, split-tf32)
    int mblocks = (NN + 127) / 128;
    {
        WPtrs wu;
        wu.w[0] = W_src_l + 0 * HID * HID;
        wu.w[1] = W_src_g + 0 * HID * HID;
        wu.w[2] = W_src_l + 2 * HID * HID;
        wu.w[3] = W_src_g + 2 * HID * HID;
        dim3 g(mblocks, 4);
        k_gemm_tf32<<<g, 256, SMEM_MMA>>>(x_user, NN, wu, p_bu, 512);
        WPtrs wi;
        wi.w[0] = W_src_l + 1 * HID * HID;
        wi.w[1] = W_src_g + 1 * HID * HID;
        wi.w[2] = nullptr; wi.w[3] = nullptr;
        dim3 g2(mblocks, 2);
        k_gemm_tf32<<<g2, 256, SMEM_MMA>>>(x_item, NN, wi, p_bi, 256);
    }

    // 5) aggregation (single pass, all relations)
    AggParams P;
    // rel0: buys (src=user)
    P.r[0].hsl = p_bu + 0;   P.r[0].hsg = p_bu + 128; P.r[0].stride = 512;
    P.r[0].asl = p_asl + 0 * NN * 4; P.r[0].asg = p_asg + 0 * NN * 4;
    P.r[0].adl = p_adl + 0 * NN * 4; P.r[0].adg = p_adg + 0 * NN * 4;
    P.r[0].rowptr = p_rowptr + 0 * (NN + 1); P.r[0].srcs = p_srcs + 0 * (EE + NN);
    P.r[0].outl = p_agg + (size_t)0 * NN * HID; P.r[0].outg = p_agg + (size_t)1 * NN * HID;
    // rel1: rev (src=item)
    P.r[1].hsl = p_bi + 0;   P.r[1].hsg = p_bi + 128; P.r[1].stride = 256;
    P.r[1].asl = p_asl + 1 * NN * 4; P.r[1].asg = p_asg + 1 * NN * 4;
    P.r[1].adl = p_adl + 1 * NN * 4; P.r[1].adg = p_adg + 1 * NN * 4;
    P.r[1].rowptr = p_rowptr + 1 * (NN + 1); P.r[1].srcs = p_srcs + 1 * (EE + NN);
    P.r[1].outl = p_agg + (size_t)2 * NN * HID; P.r[1].outg = p_agg + (size_t)3 * NN * HID;
    // rel2: follows (src=user)
    P.r[2].hsl = p_bu + 256; P.r[2].hsg = p_bu + 384; P.r[2].stride = 512;
    P.r[2].asl = p_asl + 2 * NN * 4; P.r[2].asg = p_asg + 2 * NN * 4;
    P.r[2].adl = p_adl + 2 * NN * 4; P.r[2].adg = p_adg + 2 * NN * 4;
    P.r[2].rowptr = p_rowptr + 2 * (NN + 1); P.r[2].srcs = p_srcs + 2 * (EE + NN);
    P.r[2].outl = p_agg + (size_t)4 * NN * HID; P.r[2].outg = p_agg + (size_t)5 * NN * HID;
    dim3 agrid((NN * 32 + 255) / 256, 3);
    k_agg_all<<<agrid, 256>>>(P);

    // 6) fuse + output projection
    k_fuse<<<NN / 32, 256, SMEM_FUSE>>>(
        p_agg + (size_t)2 * NN * HID, p_agg + (size_t)3 * NN * HID,
        p_agg + (size_t)4 * NN * HID, p_agg + (size_t)5 * NN * HID,
        bias_l + 1 * HID, bias_g + 1 * HID, bias_l + 2 * HID, bias_g + 2 * HID,
        relgates, gate_W, gate_b, out_W, outp);
    k_fuse<<<NN / 32, 256, SMEM_FUSE>>>(
        p_agg + (size_t)0 * NN * HID, p_agg + (size_t)1 * NN * HID,
        nullptr, nullptr,
        bias_l, bias_g, nullptr, nullptr,
        nullptr, gate_W + 256 * 128, gate_b + 128, out_W + 128 * 128,
        outp + (size_t)NN * HID);
}